// round 1
// baseline (speedup 1.0000x reference)
#include <cuda_runtime.h>
#include <math.h>

#define NSAMP 32768
#define NFRM  127
#define NB    4
#define WIN   512
#define STEP  256
#define DTRUNC 2048
#define CHUNK 4096

__device__ float g_frames[NB*NFRM*WIN];
__device__ unsigned long long g_key[NB*NFRM];
__device__ float g_Y[NB*NSAMP];

// ---------------------------------------------------------------------------
// prep: windowed frames, zero Y, init argmax keys
// ---------------------------------------------------------------------------
__global__ void k_prep(const float* __restrict__ recon) {
    int i = blockIdx.x * blockDim.x + threadIdx.x;
    if (i < NB*NFRM*WIN) {
        int t = i & (WIN-1);
        int f = (i >> 9) % NFRM;
        int b = i / (NFRM*WIN);
        float wv = (float)(0.54 - 0.46 * cos(2.0 * M_PI * (double)t / (double)WIN));
        g_frames[i] = wv * recon[b*NSAMP + f*STEP + t];
    }
    if (i < NB*NFRM) g_key[i] = 0ull;
    if (i < NB*NSAMP) g_Y[i] = 0.f;
}

// order-preserving encoding of float for unsigned max
__device__ __forceinline__ unsigned encf(float v) {
    unsigned b = __float_as_uint(v);
    return (b & 0x80000000u) ? ~b : (b | 0x80000000u);
}

// ---------------------------------------------------------------------------
// conv + argmax: fm[f][m] = sum_t a[t]*target[m-t], track argmax per frame
// ---------------------------------------------------------------------------
__global__ void __launch_bounds__(256) k_conv(const float* __restrict__ target) {
    __shared__ float sm_t[CHUNK + WIN];
    __shared__ float sm_a[WIN];
    __shared__ unsigned long long red[256];
    const int b = blockIdx.z, f = blockIdx.y;
    const int m0 = blockIdx.x * CHUNK;
    const int tid = threadIdx.x;
    const float* tb = target + b*NSAMP;

    for (int i = tid; i < CHUNK + WIN; i += 256) {
        int g = m0 - WIN + i;                // sm_t[i] <-> target[m0-512+i]
        sm_t[i] = (g >= 0) ? tb[g] : 0.f;    // zero-pad below 0 (handles m<512 edge)
    }
    for (int i = tid; i < WIN; i += 256) sm_a[i] = g_frames[(b*NFRM + f)*WIN + i];
    __syncthreads();

    const int R = 16;
    float acc[R], w[R];
    const int base = tid*R + WIN;            // sliding window base in sm_t
    #pragma unroll
    for (int j = 0; j < R; ++j) { acc[j] = 0.f; w[j] = sm_t[base + j]; }

    #pragma unroll 16
    for (int t = 0; t < WIN; ++t) {
        float av = sm_a[t];
        #pragma unroll
        for (int j = R-1; j >= 1; --j) {
            acc[j] = fmaf(av, w[j], acc[j]);
            w[j] = w[j-1];                   // window slides left as t grows
        }
        acc[0] = fmaf(av, w[0], acc[0]);
        w[0] = sm_t[base - 1 - t];           // at t=511 reads sm_t[tid*16] (in range)
    }

    unsigned long long best = 0ull;
    #pragma unroll
    for (int j = 0; j < R; ++j) {
        unsigned m = (unsigned)(m0 + tid*R + j);
        unsigned long long key = ((unsigned long long)encf(acc[j]) << 32)
                               | (unsigned long long)(0xFFFFFFFFu - m); // first-occurrence tiebreak
        if (key > best) best = key;
    }
    red[tid] = best;
    __syncthreads();
    for (int s = 128; s > 0; s >>= 1) {
        if (tid < s) { if (red[tid+s] > red[tid]) red[tid] = red[tid+s]; }
        __syncthreads();
    }
    if (tid == 0) atomicMax(&g_key[b*NFRM + f], red[0]);
}

// ---------------------------------------------------------------------------
// synth: positioned frame = frame (x) h_delta placed at integer offset p.
// Exact reference fft_shift kernel:
//   phase(k) = e^{-2pi i k (p/2)/32769} = e^{-2pi i k p/65536} * e^{+2pi i k d/65536},
//   d = 2p/65538;  h[m] = (-1)^m sin(pi d) cot(pi (m+d)/65536) / 65536
// truncated at |m| <= DTRUNC (tail energy ~1/(pi^2 D) -> rel-MSE err ~1e-4).
// ---------------------------------------------------------------------------
__global__ void __launch_bounds__(256) k_synth() {
    __shared__ float h_s[2*DTRUNC + 1];
    __shared__ float a_s[WIN];
    const int f = blockIdx.x, b = blockIdx.y;
    const int tid = threadIdx.x;

    unsigned long long key = g_key[b*NFRM + f];
    const int p = (int)(0xFFFFFFFFu - (unsigned)(key & 0xFFFFFFFFull));
    const double delta = 2.0 * (double)p / 65538.0;
    const double sd = sinpi(delta);

    for (int i = tid; i < 2*DTRUNC + 1; i += 256) {
        int m = i - DTRUNC;
        float h;
        if (p == 0) {
            h = (m == 0) ? 1.f : 0.f;
        } else {
            double arg = ((double)m + delta) / 65536.0;
            double v = sd * (cospi(arg) / sinpi(arg)) / 65536.0;
            h = (float)((m & 1) ? -v : v);
        }
        h_s[i] = h;
    }
    for (int i = tid; i < WIN; i += 256) a_s[i] = g_frames[(b*NFRM + f)*WIN + i];
    __syncthreads();

    for (int xi = tid; xi < WIN + 2*DTRUNC; xi += 256) {
        int x = p - DTRUNC + xi;             // output sample; crop to [0, NSAMP)
        if (x < 0 || x >= NSAMP) continue;
        int t0 = max(0, xi - 2*DTRUNC);
        int t1 = min(WIN-1, xi);
        float y = 0.f;
        for (int t = t0; t <= t1; ++t)
            y = fmaf(a_s[t], h_s[xi - t], y);
        atomicAdd(&g_Y[b*NSAMP + x], y);
    }
}

// ---------------------------------------------------------------------------
// mse: single-block deterministic reduction in double
// ---------------------------------------------------------------------------
__global__ void k_mse(const float* __restrict__ target, float* __restrict__ out) {
    __shared__ double red[256];
    const int tid = threadIdx.x;
    double s = 0.0;
    for (int i = tid; i < NB*NSAMP; i += 256) {
        double d = (double)g_Y[i] - (double)target[i];
        s += d * d;
    }
    red[tid] = s;
    __syncthreads();
    for (int st = 128; st > 0; st >>= 1) {
        if (tid < st) red[tid] += red[tid + st];
        __syncthreads();
    }
    if (tid == 0) out[0] = (float)(red[0] / (double)(NB*NSAMP));
}

extern "C" void kernel_launch(void* const* d_in, const int* in_sizes, int n_in,
                              void* d_out, int out_size) {
    const float* recon  = (const float*)d_in[0];
    const float* target = (const float*)d_in[1];
    float* out = (float*)d_out;
    (void)in_sizes; (void)n_in; (void)out_size;

    k_prep<<<(NB*NFRM*WIN + 255)/256, 256>>>(recon);
    k_conv<<<dim3(NSAMP/CHUNK, NFRM, NB), 256>>>(target);
    k_synth<<<dim3(NFRM, NB), 256>>>();
    k_mse<<<1, 256>>>(target, out);
}

// round 2
// speedup vs baseline: 3.1826x; 3.1826x over previous
#include <cuda_runtime.h>
#include <math.h>

#define NSAMP 32768
#define NFRM  127
#define NB    4
#define WIN   512
#define STEP  256
#define DTRUNC 1024
#define CHUNK 4096
#define TPAD  8                      // front zero-pad of target tile (keeps prefetch in-range)

__device__ float g_frames[NB*NFRM*WIN];
__device__ unsigned long long g_key[NB*NFRM];
__device__ float g_Y[NB*NSAMP];
__device__ double g_sum;

// ---------------- f32x2 packed helpers ----------------
__device__ __forceinline__ unsigned long long pk(float lo, float hi) {
    unsigned long long r;
    asm("mov.b64 %0, {%1, %2};" : "=l"(r) : "f"(lo), "f"(hi));
    return r;
}
__device__ __forceinline__ void upk(unsigned long long v, float& lo, float& hi) {
    asm("mov.b64 {%0, %1}, %2;" : "=f"(lo), "=f"(hi) : "l"(v));
}
__device__ __forceinline__ unsigned long long ffma2(unsigned long long a,
                                                    unsigned long long b,
                                                    unsigned long long c) {
    unsigned long long d;
    asm("fma.rn.f32x2 %0, %1, %2, %3;" : "=l"(d) : "l"(a), "l"(b), "l"(c));
    return d;
}

// ---------------------------------------------------------------------------
// prep: windowed frames, zero Y / keys / sum
// ---------------------------------------------------------------------------
__global__ void k_prep(const float* __restrict__ recon) {
    int i = blockIdx.x * blockDim.x + threadIdx.x;
    if (i < NB*NFRM*WIN) {
        int t = i & (WIN-1);
        int f = (i >> 9) % NFRM;
        int b = i / (NFRM*WIN);
        float wv = (float)(0.54 - 0.46 * cos(2.0 * M_PI * (double)t / (double)WIN));
        g_frames[i] = wv * recon[b*NSAMP + f*STEP + t];
    }
    if (i < NB*NFRM) g_key[i] = 0ull;
    if (i < NB*NSAMP) g_Y[i] = 0.f;
    if (i == 0) g_sum = 0.0;
}

// order-preserving encoding of float for unsigned max
__device__ __forceinline__ unsigned encf(float v) {
    unsigned b = __float_as_uint(v);
    return (b & 0x80000000u) ? ~b : (b | 0x80000000u);
}

// ---------------------------------------------------------------------------
// conv + argmax via packed f32x2: fm[f][m] = sum_t a[t]*target[m-t]
// acc2.lo accumulates even-t terms, acc2.hi odd-t terms.
// ---------------------------------------------------------------------------
__global__ void __launch_bounds__(256) k_conv(const float* __restrict__ target) {
    __shared__ float sm_t[TPAD + CHUNK + WIN];
    __shared__ float sm_a[WIN];
    __shared__ unsigned long long red[256];
    const int b = blockIdx.z, f = blockIdx.y;
    const int m0 = blockIdx.x * CHUNK;
    const int tid = threadIdx.x;
    const float* tb = target + b*NSAMP;

    for (int i = tid; i < TPAD + CHUNK + WIN; i += 256) {
        int g = m0 - WIN + (i - TPAD);          // sm_t[TPAD+k] <-> target[m0-512+k]
        sm_t[i] = (i >= TPAD && g >= 0) ? tb[g] : 0.f;
    }
    for (int i = tid; i < WIN; i += 256) sm_a[i] = g_frames[(b*NFRM + f)*WIN + i];
    __syncthreads();

    const int R = 16;
    const int base = TPAD + tid*R + WIN;        // even
    unsigned long long ACC[R], W[R];
    // invariant at top of step t (even): W[j] = { sm_t[base+j-t], sm_t[base+j-t-1] }
    #pragma unroll
    for (int j = 0; j < R; ++j) {
        ACC[j] = 0ull;
        W[j] = pk(sm_t[base + j], sm_t[base + j - 1]);
    }
    float2 q = *(const float2*)(sm_t + base - 2);   // Q(t=0)
    float qlo = q.x, qhi = q.y;

    #pragma unroll 8
    for (int t = 0; t < WIN; t += 2) {
        float2 av = *(const float2*)(sm_a + t);     // {a[t], a[t+1]}
        unsigned long long A2 = pk(av.x, av.y);
        #pragma unroll
        for (int j = 0; j < R; ++j) ACC[j] = ffma2(A2, W[j], ACC[j]);

        float2 qn = *(const float2*)(sm_t + base - 4 - t);  // Q(t+2), >= index 6 always
        #pragma unroll
        for (int j = R-1; j >= 2; --j) W[j] = W[j-2];
        W[1] = pk(qhi, qlo);
        W[0] = pk(qlo, qn.y);
        qlo = qn.x; qhi = qn.y;
    }

    unsigned long long best = 0ull;
    #pragma unroll
    for (int j = 0; j < R; ++j) {
        float lo, hi; upk(ACC[j], lo, hi);
        float v = lo + hi;
        unsigned m = (unsigned)(m0 + tid*R + j);
        unsigned long long key = ((unsigned long long)encf(v) << 32)
                               | (unsigned long long)(0xFFFFFFFFu - m);
        if (key > best) best = key;
    }
    red[tid] = best;
    __syncthreads();
    for (int s = 128; s > 0; s >>= 1) {
        if (tid < s) { if (red[tid+s] > red[tid]) red[tid] = red[tid+s]; }
        __syncthreads();
    }
    if (tid == 0) atomicMax(&g_key[b*NFRM + f], red[0]);
}

// ---------------------------------------------------------------------------
// synth: positioned frame = frame (x) h placed at integer offset p.
//   phase(k) = e^{-2pi i k (p/2)/32769} = delay p (mod 65536) * frac advance d,
//   d = 2p/65538;  h[m] = (-1)^m sin(pi d) cot(pi (m+d)/65536) / 65536
// truncated at |m| <= DTRUNC. Shift-register conv, R2=10 outputs/thread.
// ---------------------------------------------------------------------------
#define NOUT (WIN + 2*DTRUNC)          // 2560
#define R2   (NOUT/256)                // 10
#define HPAD 512
#define HLEN (HPAD + 2*DTRUNC + 1 + HPAD)   // 3073

__global__ void __launch_bounds__(256) k_synth() {
    __shared__ float hp[HLEN];
    __shared__ float a_s[WIN];
    const int f = blockIdx.x, b = blockIdx.y;
    const int tid = threadIdx.x;

    unsigned long long key = g_key[b*NFRM + f];
    const int p = (int)(0xFFFFFFFFu - (unsigned)(key & 0xFFFFFFFFull));
    const float delta = (float)(2.0 * (double)p / 65538.0);
    const float sd = sinpif(delta);

    for (int i = tid; i < HLEN; i += 256) {
        int k = i - HPAD;              // h_s index; valid [0, 2*DTRUNC]
        float h = 0.f;
        if (k >= 0 && k <= 2*DTRUNC) {
            int m = k - DTRUNC;
            if (p == 0) {
                h = (m == 0) ? 1.f : 0.f;
            } else {
                float arg = ((float)m + delta) * (1.0f / 65536.0f);
                float v = sd * (cospif(arg) / sinpif(arg)) * (1.0f / 65536.0f);
                h = (m & 1) ? -v : v;
            }
        }
        hp[i] = h;
    }
    for (int i = tid; i < WIN; i += 256) a_s[i] = g_frames[(b*NFRM + f)*WIN + i];
    __syncthreads();

    const int xi0 = tid * R2;
    float acc[R2], w[R2];
    #pragma unroll
    for (int j = 0; j < R2; ++j) { acc[j] = 0.f; w[j] = hp[HPAD + xi0 + j]; }

    #pragma unroll 10
    for (int t = 0; t < WIN; ++t) {
        float av = a_s[t];
        #pragma unroll
        for (int j = R2-1; j >= 1; --j) {
            acc[j] = fmaf(av, w[j], acc[j]);
            w[j] = w[j-1];
        }
        acc[0] = fmaf(av, w[0], acc[0]);
        w[0] = hp[HPAD + xi0 - 1 - t];          // min index: 512 - 512 = 0
    }

    #pragma unroll
    for (int j = 0; j < R2; ++j) {
        int x = p - DTRUNC + xi0 + j;
        if (x >= 0 && x < NSAMP)
            atomicAdd(&g_Y[b*NSAMP + x], acc[j]);
    }
}

// ---------------------------------------------------------------------------
// mse: multi-block reduction, double atomics, tiny finalize
// ---------------------------------------------------------------------------
__global__ void k_mse(const float* __restrict__ target) {
    __shared__ double red[256];
    const int tid = threadIdx.x;
    double s = 0.0;
    for (int i = blockIdx.x*256 + tid; i < NB*NSAMP; i += gridDim.x*256) {
        double d = (double)g_Y[i] - (double)target[i];
        s += d * d;
    }
    red[tid] = s;
    __syncthreads();
    for (int st = 128; st > 0; st >>= 1) {
        if (tid < st) red[tid] += red[tid + st];
        __syncthreads();
    }
    if (tid == 0) atomicAdd(&g_sum, red[0]);
}

__global__ void k_fin(float* __restrict__ out) {
    out[0] = (float)(g_sum / (double)(NB*NSAMP));
}

extern "C" void kernel_launch(void* const* d_in, const int* in_sizes, int n_in,
                              void* d_out, int out_size) {
    const float* recon  = (const float*)d_in[0];
    const float* target = (const float*)d_in[1];
    float* out = (float*)d_out;
    (void)in_sizes; (void)n_in; (void)out_size;

    k_prep<<<(NB*NFRM*WIN + 255)/256, 256>>>(recon);
    k_conv<<<dim3(NSAMP/CHUNK, NFRM, NB), 256>>>(target);
    k_synth<<<dim3(NFRM, NB), 256>>>();
    k_mse<<<64, 256>>>(target);
    k_fin<<<1, 1>>>(out);
}

// round 4
// speedup vs baseline: 4.8458x; 1.5226x over previous
#include <cuda_runtime.h>
#include <cuda_fp16.h>
#include <math.h>

#define NSAMP 32768
#define NFRM  127
#define MPAD  128
#define NB    4
#define WIN   512
#define STEP  256
#define DTRUNC 1024
#define PADT  512
#define LPAD  (PADT + NSAMP)

#define NT    128           // lag-tile width per block
#define KC    128           // K chunk staged in SMEM
#define CSTR  664           // shifted-copy stride (elements)
#define MTILES (NSAMP/NT)   // 256

__device__ float g_frames[NB*NFRM*WIN];
__device__ __half g_ah[NB*MPAD*WIN];
__device__ __half g_al[NB*MPAD*WIN];
__device__ __half g_th[NB*LPAD + 16];
__device__ __half g_tl[NB*LPAD + 16];
__device__ unsigned long long g_key[NB*NFRM];
__device__ float g_Y[NB*NSAMP];
__device__ double g_sum;

// ---------------- helpers ----------------
__device__ __forceinline__ unsigned smem_u32(const void* p) {
    unsigned a;
    asm("{ .reg .u64 t; cvta.to.shared.u64 t, %1; cvt.u32.u64 %0, t; }" : "=r"(a) : "l"(p));
    return a;
}
__device__ __forceinline__ unsigned encf(float v) {
    unsigned b = __float_as_uint(v);
    return (b & 0x80000000u) ? ~b : (b | 0x80000000u);
}

#define LDSM_X4(r, addr) \
    asm volatile("ldmatrix.sync.aligned.m8n8.x4.shared.b16 {%0,%1,%2,%3}, [%4];" \
        : "=r"((r)[0]), "=r"((r)[1]), "=r"((r)[2]), "=r"((r)[3]) : "r"(addr))
#define LDSM_X4T(r, addr) \
    asm volatile("ldmatrix.sync.aligned.m8n8.x4.trans.shared.b16 {%0,%1,%2,%3}, [%4];" \
        : "=r"((r)[0]), "=r"((r)[1]), "=r"((r)[2]), "=r"((r)[3]) : "r"(addr))
#define MMA16816(d, a, b0, b1) \
    asm volatile("mma.sync.aligned.m16n8k16.row.col.f32.f16.f16.f32 " \
        "{%0,%1,%2,%3}, {%4,%5,%6,%7}, {%8,%9}, {%0,%1,%2,%3};" \
        : "+f"((d)[0]), "+f"((d)[1]), "+f"((d)[2]), "+f"((d)[3]) \
        : "r"((a)[0]), "r"((a)[1]), "r"((a)[2]), "r"((a)[3]), "r"(b0), "r"(b1))

// ---------------------------------------------------------------------------
// prep: windowed frames (fp32 + fp16 hi/lo split), padded target hi/lo split
// ---------------------------------------------------------------------------
__global__ void k_prep(const float* __restrict__ recon, const float* __restrict__ target) {
    int i = blockIdx.x * blockDim.x + threadIdx.x;
    if (i < NB*MPAD*WIN) {
        int t = i & (WIN-1);
        int f = (i >> 9) & (MPAD-1);
        int b = i >> 16;
        float v = 0.f;
        if (f < NFRM) {
            float wv = (float)(0.54 - 0.46 * cos(2.0 * M_PI * (double)t / (double)WIN));
            v = wv * recon[b*NSAMP + f*STEP + t];
            g_frames[(b*NFRM + f)*WIN + t] = v;
        }
        __half hi = __float2half(v);
        g_ah[i] = hi;
        g_al[i] = __float2half(v - __half2float(hi));
    }
    if (i < NB*LPAD) {
        int b = i / LPAD, j = i - b*LPAD;
        float tv = (j >= PADT) ? target[b*NSAMP + j - PADT] : 0.f;
        __half hi = __float2half(tv);
        g_th[i] = hi;
        g_tl[i] = __float2half(tv - __half2float(hi));
    }
    if (i < 16) { g_th[NB*LPAD + i] = __float2half(0.f); g_tl[NB*LPAD + i] = __float2half(0.f); }
    if (i < NB*NFRM) g_key[i] = 0ull;
    if (i < NB*NSAMP) g_Y[i] = 0.f;
    if (i == 0) g_sum = 0.0;
}

// ---------------------------------------------------------------------------
// mma.sync Toeplitz GEMM + argmax.
// D[f][n] = sum_k A[f][k] * t[m0+n-k];  3-pass fp16 split, fp32 reg accum.
// B never materialized: ldmatrix.trans reads 16B rows straight out of 8
// byte-shifted copies of the target slice (copy choice = alignment residue).
// ---------------------------------------------------------------------------
__global__ void __launch_bounds__(256) k_conv_mma() {
    __shared__ __align__(16) __half smA[MPAD*KC];     // swizzled A chunk
    __shared__ __align__(16) __half smT[8*CSTR];      // shifted target copies
    __shared__ unsigned long long red[MPAD];

    const int tid = threadIdx.x, lane = tid & 31, warp = tid >> 5;
    const int b = blockIdx.y, m0 = blockIdx.x * NT;
    const int wm = warp & 3, wn = warp >> 2;          // 4 M-warps x 2 N-warps
    const int mbase = wm*32, nbase = wn*64;
    const int idx = lane & 15, half = lane >> 4;
    const unsigned sA = smem_u32(smA), sT = smem_u32(smT);

    if (tid < MPAD) red[tid] = 0ull;

    float acc[2][8][4];
    #pragma unroll
    for (int mi = 0; mi < 2; ++mi)
        #pragma unroll
        for (int nj = 0; nj < 8; ++nj)
            #pragma unroll
            for (int e = 0; e < 4; ++e) acc[mi][nj][e] = 0.f;

    const int rowA0 = mbase + idx, rowA1 = mbase + 16 + idx;
    const unsigned aB0 = sA + rowA0*(KC*2), swz0 = (unsigned)(rowA0 & 7);
    const unsigned aB1 = sA + rowA1*(KC*2), swz1 = (unsigned)(rowA1 & 7);

    // B ldmatrix base: element e = 512 - krow + ncol; copy c makes it 16B aligned
    const int c8 = (8 - (idx & 7)) & 7;
    const unsigned P = sT + (unsigned)(c8*(CSTR*2))
                     + (unsigned)((512 - idx + nbase + 8*half - c8) * 2);

    for (int pass = 0; pass < 3; ++pass) {
        const __half* asrc = ((pass == 1) ? g_al : g_ah) + b*MPAD*WIN;
        if (pass == 0 || pass == 2) {
            if (pass == 2) __syncthreads();            // pass-1 ldmatrix done
            const __half* tsrc = ((pass == 2) ? g_tl : g_th) + b*LPAD + m0;
            #pragma unroll
            for (int c = 0; c < 8; ++c)
                for (int i = tid; i < 648; i += 256)
                    smT[c*CSTR + i] = tsrc[i + c];
        }
        for (int ch = 0; ch < 4; ++ch) {
            __syncthreads();                           // prev chunk mma done / copies ready
            #pragma unroll
            for (int r = 0; r < 8; ++r) {              // stage A chunk (swizzled)
                int i = tid + 256*r;
                int m = i >> 4, u = i & 15;
                uint4 v = *(const uint4*)(asrc + m*WIN + ch*KC + u*8);
                *(uint4*)((char*)smA + m*(KC*2) + ((((unsigned)u) ^ (m & 7)) << 4)) = v;
            }
            __syncthreads();
            #pragma unroll
            for (int s = 0; s < 8; ++s) {
                const int S = ch*8 + s;                // k16-step within pass
                unsigned a0[4], a1[4], bb[4][4];
                unsigned u = (unsigned)(2*s + half);
                LDSM_X4(a0, aB0 + ((u ^ swz0) << 4));
                LDSM_X4(a1, aB1 + ((u ^ swz1) << 4));
                unsigned baddr = P - 32u*(unsigned)S;
                LDSM_X4T(bb[0], baddr);
                LDSM_X4T(bb[1], baddr + 32u);
                LDSM_X4T(bb[2], baddr + 64u);
                LDSM_X4T(bb[3], baddr + 96u);
                #pragma unroll
                for (int j = 0; j < 4; ++j) {
                    MMA16816(acc[0][2*j],   a0, bb[j][0], bb[j][1]);
                    MMA16816(acc[0][2*j+1], a0, bb[j][2], bb[j][3]);
                    MMA16816(acc[1][2*j],   a1, bb[j][0], bb[j][1]);
                    MMA16816(acc[1][2*j+1], a1, bb[j][2], bb[j][3]);
                }
            }
        }
    }

    // epilogue: per-row argmax keys -> quad shfl -> shared atomicMax -> global
    const int c0 = (lane & 3) * 2, r0 = lane >> 2;
    #pragma unroll
    for (int mi = 0; mi < 2; ++mi) {
        #pragma unroll
        for (int q = 0; q < 2; ++q) {
            unsigned long long best = 0ull;
            #pragma unroll
            for (int nj = 0; nj < 8; ++nj) {
                #pragma unroll
                for (int e = 0; e < 2; ++e) {
                    float v = acc[mi][nj][q*2 + e];
                    unsigned m = (unsigned)(m0 + nbase + 8*nj + c0 + e);
                    unsigned long long key = ((unsigned long long)encf(v) << 32)
                                           | (unsigned long long)(0xFFFFFFFFu - m);
                    if (key > best) best = key;
                }
            }
            unsigned long long o;
            o = __shfl_xor_sync(0xFFFFFFFFu, best, 1); if (o > best) best = o;
            o = __shfl_xor_sync(0xFFFFFFFFu, best, 2); if (o > best) best = o;
            if ((lane & 3) == 0)
                atomicMax(&red[mbase + 16*mi + 8*q + r0], best);
        }
    }
    __syncthreads();
    if (tid < NFRM) {
        unsigned long long v = red[tid];
        if (v) atomicMax(&g_key[b*NFRM + tid], v);
    }
}

// ---------------------------------------------------------------------------
// synth: positioned frame = frame (x) h placed at integer offset p.
//   d = 2p/65538;  h[m] = (-1)^m sin(pi d) cot(pi (m+d)/65536) / 65536
// ---------------------------------------------------------------------------
#define NOUT (WIN + 2*DTRUNC)
#define R2   (NOUT/256)
#define HPAD 512
#define HLEN (HPAD + 2*DTRUNC + 1 + HPAD)

__global__ void __launch_bounds__(256) k_synth() {
    __shared__ float hp[HLEN];
    __shared__ float a_s[WIN];
    const int f = blockIdx.x, b = blockIdx.y;
    const int tid = threadIdx.x;

    unsigned long long key = g_key[b*NFRM + f];
    const int p = (int)(0xFFFFFFFFu - (unsigned)(key & 0xFFFFFFFFull));
    const float delta = (float)(2.0 * (double)p / 65538.0);
    const float sd = sinpif(delta);

    for (int i = tid; i < HLEN; i += 256) {
        int k = i - HPAD;
        float h = 0.f;
        if (k >= 0 && k <= 2*DTRUNC) {
            int m = k - DTRUNC;
            if (p == 0) {
                h = (m == 0) ? 1.f : 0.f;
            } else {
                float arg = ((float)m + delta) * (1.0f / 65536.0f);
                float v = sd * (cospif(arg) / sinpif(arg)) * (1.0f / 65536.0f);
                h = (m & 1) ? -v : v;
            }
        }
        hp[i] = h;
    }
    for (int i = tid; i < WIN; i += 256) a_s[i] = g_frames[(b*NFRM + f)*WIN + i];
    __syncthreads();

    const int xi0 = tid * R2;
    float acc[R2], w[R2];
    #pragma unroll
    for (int j = 0; j < R2; ++j) { acc[j] = 0.f; w[j] = hp[HPAD + xi0 + j]; }

    #pragma unroll 10
    for (int t = 0; t < WIN; ++t) {
        float av = a_s[t];
        #pragma unroll
        for (int j = R2-1; j >= 1; --j) {
            acc[j] = fmaf(av, w[j], acc[j]);
            w[j] = w[j-1];
        }
        acc[0] = fmaf(av, w[0], acc[0]);
        w[0] = hp[HPAD + xi0 - 1 - t];
    }

    #pragma unroll
    for (int j = 0; j < R2; ++j) {
        int x = p - DTRUNC + xi0 + j;
        if (x >= 0 && x < NSAMP)
            atomicAdd(&g_Y[b*NSAMP + x], acc[j]);
    }
}

// ---------------------------------------------------------------------------
// mse + finalize
// ---------------------------------------------------------------------------
__global__ void k_mse(const float* __restrict__ target) {
    __shared__ double red[256];
    const int tid = threadIdx.x;
    double s = 0.0;
    for (int i = blockIdx.x*256 + tid; i < NB*NSAMP; i += gridDim.x*256) {
        double d = (double)g_Y[i] - (double)target[i];
        s += d * d;
    }
    red[tid] = s;
    __syncthreads();
    for (int st = 128; st > 0; st >>= 1) {
        if (tid < st) red[tid] += red[tid + st];
        __syncthreads();
    }
    if (tid == 0) atomicAdd(&g_sum, red[0]);
}

__global__ void k_fin(float* __restrict__ out) {
    out[0] = (float)(g_sum / (double)(NB*NSAMP));
}

extern "C" void kernel_launch(void* const* d_in, const int* in_sizes, int n_in,
                              void* d_out, int out_size) {
    const float* recon  = (const float*)d_in[0];
    const float* target = (const float*)d_in[1];
    float* out = (float*)d_out;
    (void)in_sizes; (void)n_in; (void)out_size;

    k_prep<<<(NB*MPAD*WIN + 255)/256, 256>>>(recon, target);
    k_conv_mma<<<dim3(MTILES, NB), 256>>>();
    k_synth<<<dim3(NFRM, NB), 256>>>();
    k_mse<<<64, 256>>>(target);
    k_fin<<<1, 1>>>(out);
}

// round 5
// speedup vs baseline: 6.8823x; 1.4203x over previous
#include <cuda_runtime.h>
#include <cuda_fp16.h>
#include <math.h>

#define NSAMP 32768
#define NFRM  127
#define MPAD  128
#define NB    4
#define WIN   512
#define STEP  256
#define DTRUNC 1024
#define PADT  512
#define LPAD  (PADT + NSAMP)

#define NT    128           // lag-tile width per block
#define KC    128           // K chunk staged in SMEM
#define CSTR  664           // shifted-copy stride (elements)
#define MTILES (NSAMP/NT)   // 256

__device__ float g_frames[NB*NFRM*WIN];
__device__ __half g_ah[NB*MPAD*WIN];
__device__ __half g_th[NB*LPAD + 16];
__device__ unsigned long long g_tkey[NB*NFRM*MTILES];
__device__ float g_Y[NB*NSAMP];
__device__ double g_sum;

// ---------------- helpers ----------------
__device__ __forceinline__ unsigned smem_u32(const void* p) {
    unsigned a;
    asm("{ .reg .u64 t; cvta.to.shared.u64 t, %1; cvt.u32.u64 %0, t; }" : "=r"(a) : "l"(p));
    return a;
}
__device__ __forceinline__ unsigned encf(float v) {
    unsigned b = __float_as_uint(v);
    return (b & 0x80000000u) ? ~b : (b | 0x80000000u);
}
__device__ __forceinline__ float decf(unsigned e) {
    return (e & 0x80000000u) ? __uint_as_float(e ^ 0x80000000u) : __uint_as_float(~e);
}

#define LDSM_X4(r, addr) \
    asm volatile("ldmatrix.sync.aligned.m8n8.x4.shared.b16 {%0,%1,%2,%3}, [%4];" \
        : "=r"((r)[0]), "=r"((r)[1]), "=r"((r)[2]), "=r"((r)[3]) : "r"(addr))
#define LDSM_X4T(r, addr) \
    asm volatile("ldmatrix.sync.aligned.m8n8.x4.trans.shared.b16 {%0,%1,%2,%3}, [%4];" \
        : "=r"((r)[0]), "=r"((r)[1]), "=r"((r)[2]), "=r"((r)[3]) : "r"(addr))
#define MMA16816(d, a, b0, b1) \
    asm volatile("mma.sync.aligned.m16n8k16.row.col.f32.f16.f16.f32 " \
        "{%0,%1,%2,%3}, {%4,%5,%6,%7}, {%8,%9}, {%0,%1,%2,%3};" \
        : "+f"((d)[0]), "+f"((d)[1]), "+f"((d)[2]), "+f"((d)[3]) \
        : "r"((a)[0]), "r"((a)[1]), "r"((a)[2]), "r"((a)[3]), "r"(b0), "r"(b1))

// ---------------------------------------------------------------------------
// prep: windowed frames (fp32 + fp16), padded fp16 target
// ---------------------------------------------------------------------------
__global__ void k_prep(const float* __restrict__ recon, const float* __restrict__ target) {
    int i = blockIdx.x * blockDim.x + threadIdx.x;
    if (i < NB*MPAD*WIN) {
        int t = i & (WIN-1);
        int f = (i >> 9) & (MPAD-1);
        int b = i >> 16;
        float v = 0.f;
        if (f < NFRM) {
            float wv = (float)(0.54 - 0.46 * cos(2.0 * M_PI * (double)t / (double)WIN));
            v = wv * recon[b*NSAMP + f*STEP + t];
            g_frames[(b*NFRM + f)*WIN + t] = v;
        }
        g_ah[i] = __float2half(v);
    }
    if (i < NB*LPAD) {
        int b = i / LPAD, j = i - b*LPAD;
        float tv = (j >= PADT) ? target[b*NSAMP + j - PADT] : 0.f;
        g_th[i] = __float2half(tv);
    }
    if (i < 16) g_th[NB*LPAD + i] = __float2half(0.f);
    if (i < NB*NSAMP) g_Y[i] = 0.f;
    if (i == 0) g_sum = 0.0;
}

// ---------------------------------------------------------------------------
// Stage 1: single-pass fp16 mma.sync Toeplitz GEMM; per-(frame,tile) best key.
// D[f][n] = sum_k A[f][k] * t[m0+n-k], fp32 accumulators.
// B never materialized: ldmatrix.trans reads 16B rows from 8 byte-shifted
// copies of the target slice (copy choice = alignment residue).
// ---------------------------------------------------------------------------
__global__ void __launch_bounds__(256) k_conv_mma() {
    __shared__ __align__(16) __half smA[MPAD*KC];     // swizzled A chunk
    __shared__ __align__(16) __half smT[8*CSTR];      // shifted target copies
    __shared__ unsigned long long red[MPAD];

    const int tid = threadIdx.x, lane = tid & 31, warp = tid >> 5;
    const int b = blockIdx.y, m0 = blockIdx.x * NT;
    const int wm = warp & 3, wn = warp >> 2;          // 4 M-warps x 2 N-warps
    const int mbase = wm*32, nbase = wn*64;
    const int idx = lane & 15, half = lane >> 4;
    const unsigned sA = smem_u32(smA), sT = smem_u32(smT);

    if (tid < MPAD) red[tid] = 0ull;

    float acc[2][8][4];
    #pragma unroll
    for (int mi = 0; mi < 2; ++mi)
        #pragma unroll
        for (int nj = 0; nj < 8; ++nj)
            #pragma unroll
            for (int e = 0; e < 4; ++e) acc[mi][nj][e] = 0.f;

    const int rowA0 = mbase + idx, rowA1 = mbase + 16 + idx;
    const unsigned aB0 = sA + rowA0*(KC*2), swz0 = (unsigned)(rowA0 & 7);
    const unsigned aB1 = sA + rowA1*(KC*2), swz1 = (unsigned)(rowA1 & 7);

    // B ldmatrix base: element e = 512 - krow + ncol; copy c makes it 16B aligned
    const int c8 = (8 - (idx & 7)) & 7;
    const unsigned P = sT + (unsigned)(c8*(CSTR*2))
                     + (unsigned)((512 - idx + nbase + 8*half - c8) * 2);

    const __half* asrc = g_ah + b*MPAD*WIN;
    {   // shifted target copies (built once)
        const __half* tsrc = g_th + b*LPAD + m0;
        #pragma unroll
        for (int c = 0; c < 8; ++c)
            for (int i = tid; i < 648; i += 256)
                smT[c*CSTR + i] = tsrc[i + c];
    }

    for (int ch = 0; ch < 4; ++ch) {
        __syncthreads();                           // smT ready / prev mma done
        #pragma unroll
        for (int r = 0; r < 8; ++r) {              // stage A chunk (swizzled)
            int i = tid + 256*r;
            int m = i >> 4, u = i & 15;
            uint4 v = *(const uint4*)(asrc + m*WIN + ch*KC + u*8);
            *(uint4*)((char*)smA + m*(KC*2) + ((((unsigned)u) ^ (m & 7)) << 4)) = v;
        }
        __syncthreads();
        #pragma unroll
        for (int s = 0; s < 8; ++s) {
            const int S = ch*8 + s;                // k16-step
            unsigned a0[4], a1[4], bb[4][4];
            unsigned u = (unsigned)(2*s + half);
            LDSM_X4(a0, aB0 + ((u ^ swz0) << 4));
            LDSM_X4(a1, aB1 + ((u ^ swz1) << 4));
            unsigned baddr = P - 32u*(unsigned)S;
            LDSM_X4T(bb[0], baddr);
            LDSM_X4T(bb[1], baddr + 32u);
            LDSM_X4T(bb[2], baddr + 64u);
            LDSM_X4T(bb[3], baddr + 96u);
            #pragma unroll
            for (int j = 0; j < 4; ++j) {
                MMA16816(acc[0][2*j],   a0, bb[j][0], bb[j][1]);
                MMA16816(acc[0][2*j+1], a0, bb[j][2], bb[j][3]);
                MMA16816(acc[1][2*j],   a1, bb[j][0], bb[j][1]);
                MMA16816(acc[1][2*j+1], a1, bb[j][2], bb[j][3]);
            }
        }
    }

    // epilogue: per-row argmax keys -> quad shfl -> shared atomicMax -> tkey
    const int c0 = (lane & 3) * 2, r0 = lane >> 2;
    #pragma unroll
    for (int mi = 0; mi < 2; ++mi) {
        #pragma unroll
        for (int q = 0; q < 2; ++q) {
            unsigned long long best = 0ull;
            #pragma unroll
            for (int nj = 0; nj < 8; ++nj) {
                #pragma unroll
                for (int e = 0; e < 2; ++e) {
                    float v = acc[mi][nj][q*2 + e];
                    unsigned m = (unsigned)(m0 + nbase + 8*nj + c0 + e);
                    unsigned long long key = ((unsigned long long)encf(v) << 32)
                                           | (unsigned long long)(0xFFFFFFFFu - m);
                    if (key > best) best = key;
                }
            }
            unsigned long long o;
            o = __shfl_xor_sync(0xFFFFFFFFu, best, 1); if (o > best) best = o;
            o = __shfl_xor_sync(0xFFFFFFFFu, best, 2); if (o > best) best = o;
            if ((lane & 3) == 0)
                atomicMax(&red[mbase + 16*mi + 8*q + r0], best);
        }
    }
    __syncthreads();
    if (tid < NFRM)
        g_tkey[(b*NFRM + tid)*MTILES + blockIdx.x] = red[tid];
}

// ---------------------------------------------------------------------------
// Stage 2 + synth (fused, one block per (frame,batch)):
//  a) exact fp32 argmax refinement over tiles within margin of the approx max
//  b) positioned frame = frame (x) h placed at integer offset p:
//     d = 2p/65538;  h[m] = (-1)^m sin(pi d) cot(pi (m+d)/65536) / 65536
// ---------------------------------------------------------------------------
#define NOUT (WIN + 2*DTRUNC)
#define R2   (NOUT/256)
#define HPAD 512
#define HLEN (HPAD + 2*DTRUNC + 1 + HPAD)

__global__ void __launch_bounds__(256) k_synth(const float* __restrict__ target) {
    __shared__ float hp[HLEN];
    __shared__ float a_s[WIN];
    __shared__ unsigned long long skey[256];
    const int f = blockIdx.x, b = blockIdx.y;
    const int tid = threadIdx.x;

    for (int i = tid; i < WIN; i += 256) a_s[i] = g_frames[(b*NFRM + f)*WIN + i];

    // ---- stage A: approx max over tile keys, threshold ----
    const unsigned long long* tk = g_tkey + (b*NFRM + f)*MTILES;
    skey[tid] = tk[tid];
    __syncthreads();
    for (int s = 128; s > 0; s >>= 1) {
        if (tid < s && skey[tid+s] > skey[tid]) skey[tid] = skey[tid+s];
        __syncthreads();
    }
    const float vmax = decf((unsigned)(skey[0] >> 32));
    const unsigned ethr = encf(vmax - 0.05f*fabsf(vmax) - 1e-3f);
    __syncthreads();

    // ---- stage B: exact fp32 recompute of qualifying tiles ----
    const float* tgt = target + b*NSAMP;
    const int lag_off = tid >> 1, halfsel = tid & 1;
    unsigned long long best = 0ull;
    for (int mt = 0; mt < MTILES; ++mt) {
        if ((unsigned)(tk[mt] >> 32) < ethr) continue;
        const int m = mt*NT + lag_off;
        float s = 0.f;
        const int t0 = halfsel*256;
        #pragma unroll 4
        for (int t = t0; t < t0 + 256; ++t) {
            int x = m - t;
            if (x >= 0) s = fmaf(a_s[t], tgt[x], s);
        }
        float o = __shfl_xor_sync(0xFFFFFFFFu, s, 1);
        float v = s + o;
        unsigned long long key = ((unsigned long long)encf(v) << 32)
                               | (unsigned long long)(0xFFFFFFFFu - (unsigned)m);
        if (halfsel == 0 && key > best) best = key;
    }
    skey[tid] = best;
    __syncthreads();
    for (int s = 128; s > 0; s >>= 1) {
        if (tid < s && skey[tid+s] > skey[tid]) skey[tid] = skey[tid+s];
        __syncthreads();
    }
    const int p = (int)(0xFFFFFFFFu - (unsigned)(skey[0] & 0xFFFFFFFFull));

    // ---- synth ----
    const float delta = (float)(2.0 * (double)p / 65538.0);
    const float sd = sinpif(delta);

    for (int i = tid; i < HLEN; i += 256) {
        int k = i - HPAD;
        float h = 0.f;
        if (k >= 0 && k <= 2*DTRUNC) {
            int m = k - DTRUNC;
            if (p == 0) {
                h = (m == 0) ? 1.f : 0.f;
            } else {
                float arg = ((float)m + delta) * (1.0f / 65536.0f);
                float v = sd * (cospif(arg) / sinpif(arg)) * (1.0f / 65536.0f);
                h = (m & 1) ? -v : v;
            }
        }
        hp[i] = h;
    }
    __syncthreads();

    const int xi0 = tid * R2;
    float acc[R2], w[R2];
    #pragma unroll
    for (int j = 0; j < R2; ++j) { acc[j] = 0.f; w[j] = hp[HPAD + xi0 + j]; }

    #pragma unroll 10
    for (int t = 0; t < WIN; ++t) {
        float av = a_s[t];
        #pragma unroll
        for (int j = R2-1; j >= 1; --j) {
            acc[j] = fmaf(av, w[j], acc[j]);
            w[j] = w[j-1];
        }
        acc[0] = fmaf(av, w[0], acc[0]);
        w[0] = hp[HPAD + xi0 - 1 - t];
    }

    #pragma unroll
    for (int j = 0; j < R2; ++j) {
        int x = p - DTRUNC + xi0 + j;
        if (x >= 0 && x < NSAMP)
            atomicAdd(&g_Y[b*NSAMP + x], acc[j]);
    }
}

// ---------------------------------------------------------------------------
// mse + finalize
// ---------------------------------------------------------------------------
__global__ void k_mse(const float* __restrict__ target) {
    __shared__ double red[256];
    const int tid = threadIdx.x;
    double s = 0.0;
    for (int i = blockIdx.x*256 + tid; i < NB*NSAMP; i += gridDim.x*256) {
        double d = (double)g_Y[i] - (double)target[i];
        s += d * d;
    }
    red[tid] = s;
    __syncthreads();
    for (int st = 128; st > 0; st >>= 1) {
        if (tid < st) red[tid] += red[tid + st];
        __syncthreads();
    }
    if (tid == 0) atomicAdd(&g_sum, red[0]);
}

__global__ void k_fin(float* __restrict__ out) {
    out[0] = (float)(g_sum / (double)(NB*NSAMP));
}

extern "C" void kernel_launch(void* const* d_in, const int* in_sizes, int n_in,
                              void* d_out, int out_size) {
    const float* recon  = (const float*)d_in[0];
    const float* target = (const float*)d_in[1];
    float* out = (float*)d_out;
    (void)in_sizes; (void)n_in; (void)out_size;

    k_prep<<<(NB*MPAD*WIN + 255)/256, 256>>>(recon, target);
    k_conv_mma<<<dim3(MTILES, NB), 256>>>();
    k_synth<<<dim3(NFRM, NB), 256>>>(target);
    k_mse<<<256, 256>>>(target);
    k_fin<<<1, 1>>>(out);
}

// round 6
// speedup vs baseline: 7.1536x; 1.0394x over previous
#include <cuda_runtime.h>
#include <cuda_fp16.h>
#include <math.h>

#define NSAMP 32768
#define NFRM  127
#define MPAD  128
#define NB    4
#define WIN   512
#define STEP  256
#define DTRUNC 256
#define PADT  512
#define LPAD  (PADT + NSAMP)

#define NT    128           // lag-tile width per block
#define KC    128           // K chunk staged in SMEM
#define CSTR  664           // shifted-copy stride (elements)
#define MTILES (NSAMP/NT)   // 256

__device__ float g_frames[NB*NFRM*WIN];
__device__ __half g_ah[NB*MPAD*WIN];
__device__ __half g_th[NB*LPAD + 16];
__device__ unsigned long long g_tkey[NB*NFRM*MTILES];
__device__ float g_Y[NB*NSAMP];
__device__ double g_sum;

// ---------------- helpers ----------------
__device__ __forceinline__ unsigned smem_u32(const void* p) {
    unsigned a;
    asm("{ .reg .u64 t; cvta.to.shared.u64 t, %1; cvt.u32.u64 %0, t; }" : "=r"(a) : "l"(p));
    return a;
}
__device__ __forceinline__ unsigned encf(float v) {
    unsigned b = __float_as_uint(v);
    return (b & 0x80000000u) ? ~b : (b | 0x80000000u);
}
__device__ __forceinline__ float decf(unsigned e) {
    return (e & 0x80000000u) ? __uint_as_float(e ^ 0x80000000u) : __uint_as_float(~e);
}

#define LDSM_X4(r, addr) \
    asm volatile("ldmatrix.sync.aligned.m8n8.x4.shared.b16 {%0,%1,%2,%3}, [%4];" \
        : "=r"((r)[0]), "=r"((r)[1]), "=r"((r)[2]), "=r"((r)[3]) : "r"(addr))
#define LDSM_X4T(r, addr) \
    asm volatile("ldmatrix.sync.aligned.m8n8.x4.trans.shared.b16 {%0,%1,%2,%3}, [%4];" \
        : "=r"((r)[0]), "=r"((r)[1]), "=r"((r)[2]), "=r"((r)[3]) : "r"(addr))
#define MMA16816(d, a, b0, b1) \
    asm volatile("mma.sync.aligned.m16n8k16.row.col.f32.f16.f16.f32 " \
        "{%0,%1,%2,%3}, {%4,%5,%6,%7}, {%8,%9}, {%0,%1,%2,%3};" \
        : "+f"((d)[0]), "+f"((d)[1]), "+f"((d)[2]), "+f"((d)[3]) \
        : "r"((a)[0]), "r"((a)[1]), "r"((a)[2]), "r"((a)[3]), "r"(b0), "r"(b1))

// ---------------------------------------------------------------------------
// prep: windowed frames (fp32 + fp16), padded fp16 target
// ---------------------------------------------------------------------------
__global__ void k_prep(const float* __restrict__ recon, const float* __restrict__ target) {
    int i = blockIdx.x * blockDim.x + threadIdx.x;
    if (i < NB*MPAD*WIN) {
        int t = i & (WIN-1);
        int f = (i >> 9) & (MPAD-1);
        int b = i >> 16;
        float v = 0.f;
        if (f < NFRM) {
            float wv = 0.54f - 0.46f * cospif((float)t * (1.0f/256.0f));
            v = wv * recon[b*NSAMP + f*STEP + t];
            g_frames[(b*NFRM + f)*WIN + t] = v;
        }
        g_ah[i] = __float2half(v);
    }
    if (i < NB*LPAD) {
        int b = i / LPAD, j = i - b*LPAD;
        float tv = (j >= PADT) ? target[b*NSAMP + j - PADT] : 0.f;
        g_th[i] = __float2half(tv);
    }
    if (i < 16) g_th[NB*LPAD + i] = __float2half(0.f);
    if (i < NB*NSAMP) g_Y[i] = 0.f;
    if (i == 0) g_sum = 0.0;
}

// ---------------------------------------------------------------------------
// Stage 1: single-pass fp16 mma.sync Toeplitz GEMM; per-(frame,tile) best key.
// D[f][n] = sum_k A[f][k] * t[m0+n-k], fp32 accumulators.
// ---------------------------------------------------------------------------
__global__ void __launch_bounds__(256) k_conv_mma() {
    __shared__ __align__(16) __half smA[MPAD*KC];     // swizzled A chunk
    __shared__ __align__(16) __half smT[8*CSTR];      // shifted target copies
    __shared__ unsigned long long red[MPAD];

    const int tid = threadIdx.x, lane = tid & 31, warp = tid >> 5;
    const int b = blockIdx.y, m0 = blockIdx.x * NT;
    const int wm = warp & 3, wn = warp >> 2;          // 4 M-warps x 2 N-warps
    const int mbase = wm*32, nbase = wn*64;
    const int idx = lane & 15, half = lane >> 4;
    const unsigned sA = smem_u32(smA), sT = smem_u32(smT);

    if (tid < MPAD) red[tid] = 0ull;

    float acc[2][8][4];
    #pragma unroll
    for (int mi = 0; mi < 2; ++mi)
        #pragma unroll
        for (int nj = 0; nj < 8; ++nj)
            #pragma unroll
            for (int e = 0; e < 4; ++e) acc[mi][nj][e] = 0.f;

    const int rowA0 = mbase + idx, rowA1 = mbase + 16 + idx;
    const unsigned aB0 = sA + rowA0*(KC*2), swz0 = (unsigned)(rowA0 & 7);
    const unsigned aB1 = sA + rowA1*(KC*2), swz1 = (unsigned)(rowA1 & 7);

    const int c8 = (8 - (idx & 7)) & 7;
    const unsigned P = sT + (unsigned)(c8*(CSTR*2))
                     + (unsigned)((512 - idx + nbase + 8*half - c8) * 2);

    const __half* asrc = g_ah + b*MPAD*WIN;
    {   // shifted target copies (built once)
        const __half* tsrc = g_th + b*LPAD + m0;
        #pragma unroll
        for (int c = 0; c < 8; ++c)
            for (int i = tid; i < 648; i += 256)
                smT[c*CSTR + i] = tsrc[i + c];
    }

    for (int ch = 0; ch < 4; ++ch) {
        __syncthreads();                           // smT ready / prev mma done
        #pragma unroll
        for (int r = 0; r < 8; ++r) {              // stage A chunk (swizzled)
            int i = tid + 256*r;
            int m = i >> 4, u = i & 15;
            uint4 v = *(const uint4*)(asrc + m*WIN + ch*KC + u*8);
            *(uint4*)((char*)smA + m*(KC*2) + ((((unsigned)u) ^ (m & 7)) << 4)) = v;
        }
        __syncthreads();
        #pragma unroll
        for (int s = 0; s < 8; ++s) {
            const int S = ch*8 + s;                // k16-step
            unsigned a0[4], a1[4], bb[4][4];
            unsigned u = (unsigned)(2*s + half);
            LDSM_X4(a0, aB0 + ((u ^ swz0) << 4));
            LDSM_X4(a1, aB1 + ((u ^ swz1) << 4));
            unsigned baddr = P - 32u*(unsigned)S;
            LDSM_X4T(bb[0], baddr);
            LDSM_X4T(bb[1], baddr + 32u);
            LDSM_X4T(bb[2], baddr + 64u);
            LDSM_X4T(bb[3], baddr + 96u);
            #pragma unroll
            for (int j = 0; j < 4; ++j) {
                MMA16816(acc[0][2*j],   a0, bb[j][0], bb[j][1]);
                MMA16816(acc[0][2*j+1], a0, bb[j][2], bb[j][3]);
                MMA16816(acc[1][2*j],   a1, bb[j][0], bb[j][1]);
                MMA16816(acc[1][2*j+1], a1, bb[j][2], bb[j][3]);
            }
        }
    }

    // epilogue: per-row argmax keys -> quad shfl -> shared atomicMax -> tkey
    const int c0 = (lane & 3) * 2, r0 = lane >> 2;
    #pragma unroll
    for (int mi = 0; mi < 2; ++mi) {
        #pragma unroll
        for (int q = 0; q < 2; ++q) {
            unsigned long long best = 0ull;
            #pragma unroll
            for (int nj = 0; nj < 8; ++nj) {
                #pragma unroll
                for (int e = 0; e < 2; ++e) {
                    float v = acc[mi][nj][q*2 + e];
                    unsigned m = (unsigned)(m0 + nbase + 8*nj + c0 + e);
                    unsigned long long key = ((unsigned long long)encf(v) << 32)
                                           | (unsigned long long)(0xFFFFFFFFu - m);
                    if (key > best) best = key;
                }
            }
            unsigned long long o;
            o = __shfl_xor_sync(0xFFFFFFFFu, best, 1); if (o > best) best = o;
            o = __shfl_xor_sync(0xFFFFFFFFu, best, 2); if (o > best) best = o;
            if ((lane & 3) == 0)
                atomicMax(&red[mbase + 16*mi + 8*q + r0], best);
        }
    }
    __syncthreads();
    if (tid < NFRM)
        g_tkey[(b*NFRM + tid)*MTILES + blockIdx.x] = red[tid];
}

// ---------------------------------------------------------------------------
// Stage 2 + synth (fused, one block per (frame,batch)):
//  a) exact fp32 argmax refinement over tiles within margin of the approx max
//  b) positioned frame = frame (x) h placed at integer offset p:
//     d = 2p/65538;  h[m] = (-1)^m sin(pi d) cot(pi (m+d)/65536) / 65536
// ---------------------------------------------------------------------------
#define NOUT (WIN + 2*DTRUNC)       // 1024
#define R2   (NOUT/256)             // 4
#define HPAD 512
#define HLEN (HPAD + NOUT)          // 1536; h nonzero only on [HPAD, HPAD+2*DTRUNC]

__global__ void __launch_bounds__(256) k_synth(const float* __restrict__ target) {
    __shared__ float hp[HLEN];
    __shared__ float a_s[WIN];
    __shared__ unsigned long long skey[256];
    const int f = blockIdx.x, b = blockIdx.y;
    const int tid = threadIdx.x;

    for (int i = tid; i < WIN; i += 256) a_s[i] = g_frames[(b*NFRM + f)*WIN + i];

    // ---- stage A: approx max over tile keys, threshold ----
    const unsigned long long* tk = g_tkey + (b*NFRM + f)*MTILES;
    skey[tid] = tk[tid];
    __syncthreads();
    for (int s = 128; s > 0; s >>= 1) {
        if (tid < s && skey[tid+s] > skey[tid]) skey[tid] = skey[tid+s];
        __syncthreads();
    }
    const float vmax = decf((unsigned)(skey[0] >> 32));
    const unsigned ethr = encf(vmax - 0.05f*fabsf(vmax) - 1e-3f);
    __syncthreads();

    // ---- stage B: exact fp32 recompute of qualifying tiles ----
    const float* tgt = target + b*NSAMP;
    const int lag_off = tid >> 1, halfsel = tid & 1;
    unsigned long long best = 0ull;
    for (int mt = 0; mt < MTILES; ++mt) {
        if ((unsigned)(tk[mt] >> 32) < ethr) continue;
        const int m = mt*NT + lag_off;
        float s = 0.f;
        const int t0 = halfsel*256;
        #pragma unroll 4
        for (int t = t0; t < t0 + 256; ++t) {
            int x = m - t;
            if (x >= 0) s = fmaf(a_s[t], tgt[x], s);
        }
        float o = __shfl_xor_sync(0xFFFFFFFFu, s, 1);
        float v = s + o;
        unsigned long long key = ((unsigned long long)encf(v) << 32)
                               | (unsigned long long)(0xFFFFFFFFu - (unsigned)m);
        if (halfsel == 0 && key > best) best = key;
    }
    skey[tid] = best;
    __syncthreads();
    for (int s = 128; s > 0; s >>= 1) {
        if (tid < s && skey[tid+s] > skey[tid]) skey[tid] = skey[tid+s];
        __syncthreads();
    }
    const int p = (int)(0xFFFFFFFFu - (unsigned)(skey[0] & 0xFFFFFFFFull));

    // ---- synth ----
    const float delta = (float)(2.0 * (double)p / 65538.0);
    const float sd = sinpif(delta);

    for (int i = tid; i < HLEN; i += 256) {
        int k = i - HPAD;
        float h = 0.f;
        if (k >= 0 && k <= 2*DTRUNC) {
            int m = k - DTRUNC;
            if (p == 0) {
                h = (m == 0) ? 1.f : 0.f;
            } else {
                float arg = ((float)m + delta) * (1.0f / 65536.0f);
                float v = sd * (cospif(arg) / sinpif(arg)) * (1.0f / 65536.0f);
                h = (m & 1) ? -v : v;
            }
        }
        hp[i] = h;
    }
    __syncthreads();

    const int xi0 = tid * R2;
    float acc[R2], w[R2];
    #pragma unroll
    for (int j = 0; j < R2; ++j) { acc[j] = 0.f; w[j] = hp[HPAD + xi0 + j]; }

    #pragma unroll 16
    for (int t = 0; t < WIN; ++t) {
        float av = a_s[t];
        #pragma unroll
        for (int j = R2-1; j >= 1; --j) {
            acc[j] = fmaf(av, w[j], acc[j]);
            w[j] = w[j-1];
        }
        acc[0] = fmaf(av, w[0], acc[0]);
        w[0] = hp[HPAD + xi0 - 1 - t];     // min index 0 at xi0=0, t=511
    }

    #pragma unroll
    for (int j = 0; j < R2; ++j) {
        int x = p - DTRUNC + xi0 + j;
        if (x >= 0 && x < NSAMP)
            atomicAdd(&g_Y[b*NSAMP + x], acc[j]);
    }
}

// ---------------------------------------------------------------------------
// mse + finalize
// ---------------------------------------------------------------------------
__global__ void k_mse(const float* __restrict__ target) {
    __shared__ double red[256];
    const int tid = threadIdx.x;
    double s = 0.0;
    for (int i = blockIdx.x*256 + tid; i < NB*NSAMP; i += gridDim.x*256) {
        double d = (double)g_Y[i] - (double)target[i];
        s += d * d;
    }
    red[tid] = s;
    __syncthreads();
    for (int st = 128; st > 0; st >>= 1) {
        if (tid < st) red[tid] += red[tid + st];
        __syncthreads();
    }
    if (tid == 0) atomicAdd(&g_sum, red[0]);
}

__global__ void k_fin(float* __restrict__ out) {
    out[0] = (float)(g_sum / (double)(NB*NSAMP));
}

extern "C" void kernel_launch(void* const* d_in, const int* in_sizes, int n_in,
                              void* d_out, int out_size) {
    const float* recon  = (const float*)d_in[0];
    const float* target = (const float*)d_in[1];
    float* out = (float*)d_out;
    (void)in_sizes; (void)n_in; (void)out_size;

    k_prep<<<(NB*MPAD*WIN + 255)/256, 256>>>(recon, target);
    k_conv_mma<<<dim3(MTILES, NB), 256>>>();
    k_synth<<<dim3(NFRM, NB), 256>>>(target);
    k_mse<<<256, 256>>>(target);
    k_fin<<<1, 1>>>(out);
}